// round 14
// baseline (speedup 1.0000x reference)
#include <cuda_runtime.h>
#include <stdint.h>

// ---------------------------------------------------------------------------
// Sparse average pooling via L2-resident presence-bitmap ranks.
//
// Effective reference key (JAX x64 disabled -> int32 wrap drops batch term):
//   q0*2^22 + q1*2^11 + q2, q_i = coord_i>>1 < 512.  27-bit keyspace.
// key = (q0<<18)|(q1<<9)|q2 (order-isomorphic). Bitmap 16MB, L2-resident.
// rank = # distinct smaller keys = jnp.unique inverse (sort-equivalent,
// verified). Ranks DENSE in [0,nvox): empty slots = contiguous tail.
//
// This round: SELF-RESTORING STATE (no bulk-zero kernel; every call leaves
// all scratch zeroed for the next) + atomic-free k_rank (dup-point list
// built in k_setbits; tiny k_mark derives multi flags/counts).
// Output stage = proven gather (sequential writes, random 256B reads).
// ---------------------------------------------------------------------------

#define NBM_WORDS (1u << 22)    // 2^27 bits / 32 = 16 MB
#define SEGW      4u            // 4 words = 128 bits per segment
#define NSEG      (NBM_WORDS / SEGW)        // 1,048,576 segments (4MB prefix)
#define CHUNK_SEGS 1024u
#define NCHUNKB   (NSEG / CHUNK_SEGS)       // 1024 scan chunks
#define MAXN      (1 << 21)

__device__ uint32_t g_bitmap[NBM_WORDS];   // zeroed by k_multi each call
__device__ uint32_t g_segpref[NSEG];       // fully rewritten each call
__device__ uint32_t g_state[NCHUNKB];      // zeroed by k_setbits each call
__device__ uint32_t g_keys[MAXN];          // fully rewritten
__device__ uint32_t g_cnt[MAXN];           // (count-1) per voxel; lazily zeroed by k_final
__device__ uint32_t g_ranks[MAXN];         // fully rewritten
__device__ uint32_t g_inv[MAXN];           // slot -> point | multi flag (bit31)
__device__ uint32_t g_dup[MAXN];           // points whose bit was already set
__device__ uint32_t g_multi[MAXN];         // worklist of multi-point voxel slots
__device__ uint32_t g_ndup;                // reset by k_mark
__device__ uint32_t g_nmulti;              // reset by k_mark (next call)
__device__ uint32_t g_nvox;                // rewritten each call

__device__ __forceinline__ uint32_t make_key(int4 c) {
    uint32_t q0 = ((uint32_t)c.x) >> 1;
    uint32_t q1 = ((uint32_t)c.y) >> 1;
    uint32_t q2 = ((uint32_t)c.z) >> 1;
    return (q0 << 18) | (q1 << 9) | q2;   // batch excluded (int32 wrap in ref)
}

__device__ __forceinline__ uint32_t popc4(uint4 v) {
    return __popc(v.x) + __popc(v.y) + __popc(v.z) + __popc(v.w);
}

// A: set presence bits + stash keys + build dup list; also zero scan state.
__global__ void k_setbits(const int4* __restrict__ coords, int n) {
    uint32_t tid = blockIdx.x * blockDim.x + threadIdx.x;
    if (tid < NCHUNKB) g_state[tid] = 0u;          // for k_scan (this call)
    if (tid >= (uint32_t)n) return;
    uint32_t key = make_key(coords[tid]);
    g_keys[tid] = key;
    uint32_t old = atomicOr(&g_bitmap[key >> 5], 1u << (key & 31u));
    if ((old >> (key & 31u)) & 1u) {               // bit already set -> dup point
        uint32_t s = atomicAdd(&g_ndup, 1u);
        g_dup[s] = tid;
    }
}

// B: fused popcount + scan, decoupled lookback. Block b handles 1024 segments;
//    writes ABSOLUTE exclusive prefix per segment.
__global__ void __launch_bounds__(256) k_scan() {
    __shared__ uint32_t sh[256];
    __shared__ uint32_t sh_excl;
    uint32_t b = blockIdx.x, t = threadIdx.x;
    uint32_t segBase = b * CHUNK_SEGS + t * 4u;   // 4 segments per thread
    const uint4* p = reinterpret_cast<const uint4*>(&g_bitmap[segBase * SEGW]);
    uint4 w0 = p[0], w1 = p[1], w2 = p[2], w3 = p[3];
    uint32_t s0 = popc4(w0);
    uint32_t s1 = popc4(w1);
    uint32_t s2 = popc4(w2);
    uint32_t s3 = popc4(w3);
    uint32_t tsum = s0 + s1 + s2 + s3;
    sh[t] = tsum;
    __syncthreads();
    for (int off = 1; off < 256; off <<= 1) {
        uint32_t v = 0;
        if ((int)t >= off) v = sh[t - off];
        __syncthreads();
        if ((int)t >= off) sh[t] += v;
        __syncthreads();
    }
    uint32_t texcl = sh[t] - tsum;

    if (t == 0) {
        uint32_t total = sh[255];
        uint32_t excl;
        if (b == 0) {
            atomicExch(&g_state[0], (total << 2) | 2u);
            excl = 0u;
        } else {
            atomicExch(&g_state[b], (total << 2) | 1u);   // aggregate ready
            uint32_t sum = 0; int i = (int)b - 1;
            while (true) {
                uint32_t v = atomicOr(&g_state[i], 0u);
                uint32_t f = v & 3u;
                if (f == 0u) { __nanosleep(20); continue; }
                sum += v >> 2;
                if (f == 2u) break;
                --i;
            }
            atomicExch(&g_state[b], ((sum + total) << 2) | 2u);  // inclusive
            excl = sum;
        }
        sh_excl = excl;
        if (b == NCHUNKB - 1) g_nvox = excl + total;
    }
    __syncthreads();
    uint32_t base = sh_excl + texcl;
    g_segpref[segBase]     = base;
    g_segpref[segBase + 1] = base + s0;
    g_segpref[segBase + 2] = base + s0 + s1;
    g_segpref[segBase + 3] = base + s0 + s1 + s2;
}

// C: per-point rank, ATOMIC-FREE: rank store + inverse-map store only.
__global__ void k_rank(int n) {
    int i = blockIdx.x * blockDim.x + threadIdx.x;
    if (i >= n) return;
    uint32_t key  = g_keys[i];
    uint32_t bit  = key & 31u;
    uint32_t w    = key >> 5;
    uint32_t seg  = w >> 2;          // 4 words per segment
    uint32_t widx = w & 3u;
    uint32_t r = g_segpref[seg];
    uint32_t mask = (1u << bit) - 1u;
    uint4 v = reinterpret_cast<const uint4*>(g_bitmap)[seg];
    uint32_t words[4] = {v.x, v.y, v.z, v.w};
#pragma unroll
    for (uint32_t idx = 0; idx < 4; idx++) {
        if (idx < widx)       r += __popc(words[idx]);
        else if (idx == widx) r += __popc(words[idx] & mask);
    }
    g_ranks[i] = r;
    g_inv[r] = (uint32_t)i;          // exact for singletons; racy (flagged) else
}

// D: single-block dup processing: per-voxel extra-count, multi worklist,
//    multi flag (bit31 of g_inv). Resets g_nmulti (start) and g_ndup (end).
__global__ void k_mark() {
    uint32_t nd = g_ndup;
    if (threadIdx.x == 0) g_nmulti = 0u;
    __syncthreads();
    for (uint32_t j = threadIdx.x; j < nd; j += blockDim.x) {
        uint32_t r = g_ranks[g_dup[j]];
        uint32_t old = atomicAdd(&g_cnt[r], 1u);
        if (old == 0u) {                     // first dup -> new multi voxel
            uint32_t s = atomicAdd(&g_nmulti, 1u);
            g_multi[s] = r;
            atomicOr(&g_inv[r], 0x80000000u);
        }
    }
    __syncthreads();
    if (threadIdx.x == 0) g_ndup = 0u;       // restore for next call
}

// E: sequential output writer. 8-lane group per slot (4 slots/warp).
//    singleton (s < nvox, flag clear) -> gather point's feats/coords;
//    else (multi or empty tail) -> zeros. Writes fully sequential.
__global__ void k_gather(const int* __restrict__ coords, const float* __restrict__ feats,
                         float* __restrict__ outc, float* __restrict__ outf, int n) {
    uint32_t gw   = (blockIdx.x * blockDim.x + threadIdx.x) >> 5;
    uint32_t lane = threadIdx.x & 31u;
    uint32_t q    = lane >> 3;            // 0..3: slot within warp
    uint32_t ql   = lane & 7u;
    uint32_t s    = gw * 4u + q;
    if (s >= (uint32_t)n) return;
    float4 v0 = make_float4(0.f, 0.f, 0.f, 0.f);
    float4 v1 = v0;
    float4 cf = v0;
    if (s < g_nvox) {
        uint32_t inv = g_inv[s];
        if (!(inv >> 31)) {               // singleton voxel
            uint32_t pt = inv;
            const float4* fin = reinterpret_cast<const float4*>(feats + 64ull * pt);
            v0 = __ldcs(fin + ql);
            v1 = __ldcs(fin + ql + 8);
            if (ql == 0u) {
                int4 cc = reinterpret_cast<const int4*>(coords)[pt];
                cf = make_float4((float)cc.x, (float)cc.y, (float)cc.z, (float)cc.w);
            }
        }
    }
    float4* fo = reinterpret_cast<float4*>(outf + 64ull * s);
    __stcs(fo + ql, v0);
    __stcs(fo + ql + 8, v1);
    if (ql == 0u)
        __stcs(reinterpret_cast<float4*>(outc + 4ull * s), cf);
}

// F: atomic accumulate for multi-voxel points (warp ballot + cooperative).
//    Also zeroes the bitmap for the next call (last reader was k_rank).
__global__ void k_multi(const int* __restrict__ coords, const float* __restrict__ feats,
                        float* __restrict__ outc, float* __restrict__ outf, int n) {
    uint32_t tid    = blockIdx.x * blockDim.x + threadIdx.x;
    uint32_t stride = gridDim.x * blockDim.x;
    uint4 z4 = make_uint4(0u, 0u, 0u, 0u);
    uint4* bm = reinterpret_cast<uint4*>(g_bitmap);
    for (uint32_t i = tid; i < NBM_WORDS / 4u; i += stride) bm[i] = z4;

    uint32_t gw   = tid >> 5;
    uint32_t lane = threadIdx.x & 31u;
    uint32_t pt   = gw * 32u + lane;
    bool valid = pt < (uint32_t)n;
    uint32_t r = valid ? g_ranks[pt] : 0u;
    bool multi = valid && (g_cnt[r] != 0u);
    uint32_t m = __ballot_sync(0xffffffffu, multi);
    while (m) {
        uint32_t j = __ffs(m) - 1u;
        m &= m - 1u;
        uint32_t rj  = __shfl_sync(0xffffffffu, r, j);
        uint32_t ptj = gw * 32u + j;
        float2 v = reinterpret_cast<const float2*>(feats + 64ull * ptj)[lane];
        float* fs = outf + 64ull * rj + 2ull * lane;
        atomicAdd(fs, v.x);
        atomicAdd(fs + 1, v.y);
        if (lane < 4u)
            atomicAdd(&outc[4ull * rj + lane], (float)coords[4ull * ptj + lane]);
    }
}

// G: finalize multi voxels from worklist (warp per voxel); count = g_cnt+1.
//    Lazily restores g_cnt to zero (only multi slots were touched).
__global__ void k_final(float* __restrict__ outc, float* __restrict__ outf) {
    uint32_t gw   = (blockIdx.x * blockDim.x + threadIdx.x) >> 5;
    uint32_t lane = threadIdx.x & 31u;
    uint32_t nw   = (gridDim.x * blockDim.x) >> 5;
    uint32_t nm   = g_nmulti;
    for (uint32_t v = gw; v < nm; v += nw) {
        uint32_t r = g_multi[v];
        float fc = (float)(g_cnt[r] + 1u);
        float* f = outf + 64ull * r + 2ull * lane;
        f[0] = f[0] / fc;
        f[1] = f[1] / fc;
        if (lane < 4u) {
            float* cc = outc + 4ull * r + lane;
            cc[0] = rintf(cc[0] / fc);   // half-to-even == jnp.round (exact sums)
        }
        if (lane == 0u) g_cnt[r] = 0u;   // restore for next call
    }
}

extern "C" void kernel_launch(void* const* d_in, const int* in_sizes, int n_in,
                              void* d_out, int out_size) {
    // coords is the smaller input (4 ints/point) vs feats (64 floats/point)
    const int*   coords;
    const float* feats;
    int n;
    if (in_sizes[0] <= in_sizes[1]) {
        coords = (const int*)d_in[0];
        feats  = (const float*)d_in[1];
        n = in_sizes[0] / 4;
    } else {
        coords = (const int*)d_in[1];
        feats  = (const float*)d_in[0];
        n = in_sizes[1] / 4;
    }
    if (n <= 0 || n > MAXN) return;

    float* outc = (float*)d_out;             // [n,4]  pooled coords (as f32)
    float* outf = outc + 4ull * (size_t)n;   // [n,64] pooled feats

    const int4* c4 = reinterpret_cast<const int4*>(coords);
    int nb = (n + 255) / 256;

    k_setbits<<<nb, 256>>>(c4, n);
    k_scan<<<NCHUNKB, 256>>>();
    k_rank<<<nb, 256>>>(n);
    k_mark<<<1, 1024>>>();
    {
        long long warps = (n + 3) / 4;
        int blocks = (int)((warps * 32 + 255) / 256);
        k_gather<<<blocks, 256>>>(coords, feats, outc, outf, n);
    }
    k_multi<<<nb, 256>>>(coords, feats, outc, outf, n);
    k_final<<<256, 256>>>(outc, outf);
}

// round 15
// speedup vs baseline: 1.0334x; 1.0334x over previous
#include <cuda_runtime.h>
#include <stdint.h>

// ---------------------------------------------------------------------------
// Sparse average pooling via L2-resident presence-bitmap ranks.
//
// Effective reference key (JAX x64 disabled -> int32 wrap drops batch term):
//   q0*2^22 + q1*2^11 + q2, q_i = coord_i>>1 < 512.  27-bit keyspace.
// key = (q0<<18)|(q1<<9)|q2 (order-isomorphic). Bitmap 16MB, L2-resident.
// rank = # distinct smaller keys = jnp.unique inverse (sort-equivalent,
// verified). Ranks DENSE in [0,nvox): empty slots = contiguous tail.
//
// Self-restoring scratch state (no bulk-zero kernel) + atomic-free k_rank
// (dup list from k_setbits). This round: k_mark parallelized across the
// grid (single-block version measured 15.5us latency-starved).
// ---------------------------------------------------------------------------

#define NBM_WORDS (1u << 22)    // 2^27 bits / 32 = 16 MB
#define SEGW      4u            // 4 words = 128 bits per segment
#define NSEG      (NBM_WORDS / SEGW)        // 1,048,576 segments (4MB prefix)
#define CHUNK_SEGS 1024u
#define NCHUNKB   (NSEG / CHUNK_SEGS)       // 1024 scan chunks
#define MAXN      (1 << 21)

__device__ uint32_t g_bitmap[NBM_WORDS];   // zeroed by k_multi each call
__device__ uint32_t g_segpref[NSEG];       // fully rewritten each call
__device__ uint32_t g_state[NCHUNKB];      // zeroed by k_setbits each call
__device__ uint32_t g_keys[MAXN];          // fully rewritten
__device__ uint32_t g_cnt[MAXN];           // (count-1) per voxel; lazily zeroed by k_final
__device__ uint32_t g_ranks[MAXN];         // fully rewritten
__device__ uint32_t g_inv[MAXN];           // slot -> point | multi flag (bit31)
__device__ uint32_t g_dup[MAXN];           // points whose bit was already set
__device__ uint32_t g_multi[MAXN];         // worklist of multi-point voxel slots
__device__ uint32_t g_ndup;                // reset by k_gather
__device__ uint32_t g_nmulti;              // reset by k_setbits
__device__ uint32_t g_nvox;                // rewritten each call

__device__ __forceinline__ uint32_t make_key(int4 c) {
    uint32_t q0 = ((uint32_t)c.x) >> 1;
    uint32_t q1 = ((uint32_t)c.y) >> 1;
    uint32_t q2 = ((uint32_t)c.z) >> 1;
    return (q0 << 18) | (q1 << 9) | q2;   // batch excluded (int32 wrap in ref)
}

__device__ __forceinline__ uint32_t popc4(uint4 v) {
    return __popc(v.x) + __popc(v.y) + __popc(v.z) + __popc(v.w);
}

// A: set presence bits + stash keys + build dup list; zero scan state;
//    reset g_nmulti (consumed by k_mark later this call).
__global__ void k_setbits(const int4* __restrict__ coords, int n) {
    uint32_t tid = blockIdx.x * blockDim.x + threadIdx.x;
    if (tid < NCHUNKB) g_state[tid] = 0u;          // for k_scan (this call)
    if (tid == 0) g_nmulti = 0u;
    if (tid >= (uint32_t)n) return;
    uint32_t key = make_key(coords[tid]);
    g_keys[tid] = key;
    uint32_t old = atomicOr(&g_bitmap[key >> 5], 1u << (key & 31u));
    if ((old >> (key & 31u)) & 1u) {               // bit already set -> dup point
        uint32_t s = atomicAdd(&g_ndup, 1u);
        g_dup[s] = tid;
    }
}

// B: fused popcount + scan, decoupled lookback. Block b handles 1024 segments;
//    writes ABSOLUTE exclusive prefix per segment.
__global__ void __launch_bounds__(256) k_scan() {
    __shared__ uint32_t sh[256];
    __shared__ uint32_t sh_excl;
    uint32_t b = blockIdx.x, t = threadIdx.x;
    uint32_t segBase = b * CHUNK_SEGS + t * 4u;   // 4 segments per thread
    const uint4* p = reinterpret_cast<const uint4*>(&g_bitmap[segBase * SEGW]);
    uint4 w0 = p[0], w1 = p[1], w2 = p[2], w3 = p[3];
    uint32_t s0 = popc4(w0);
    uint32_t s1 = popc4(w1);
    uint32_t s2 = popc4(w2);
    uint32_t s3 = popc4(w3);
    uint32_t tsum = s0 + s1 + s2 + s3;
    sh[t] = tsum;
    __syncthreads();
    for (int off = 1; off < 256; off <<= 1) {
        uint32_t v = 0;
        if ((int)t >= off) v = sh[t - off];
        __syncthreads();
        if ((int)t >= off) sh[t] += v;
        __syncthreads();
    }
    uint32_t texcl = sh[t] - tsum;

    if (t == 0) {
        uint32_t total = sh[255];
        uint32_t excl;
        if (b == 0) {
            atomicExch(&g_state[0], (total << 2) | 2u);
            excl = 0u;
        } else {
            atomicExch(&g_state[b], (total << 2) | 1u);   // aggregate ready
            uint32_t sum = 0; int i = (int)b - 1;
            while (true) {
                uint32_t v = atomicOr(&g_state[i], 0u);
                uint32_t f = v & 3u;
                if (f == 0u) { __nanosleep(20); continue; }
                sum += v >> 2;
                if (f == 2u) break;
                --i;
            }
            atomicExch(&g_state[b], ((sum + total) << 2) | 2u);  // inclusive
            excl = sum;
        }
        sh_excl = excl;
        if (b == NCHUNKB - 1) g_nvox = excl + total;
    }
    __syncthreads();
    uint32_t base = sh_excl + texcl;
    g_segpref[segBase]     = base;
    g_segpref[segBase + 1] = base + s0;
    g_segpref[segBase + 2] = base + s0 + s1;
    g_segpref[segBase + 3] = base + s0 + s1 + s2;
}

// C: per-point rank, ATOMIC-FREE: rank store + inverse-map store only.
__global__ void k_rank(int n) {
    int i = blockIdx.x * blockDim.x + threadIdx.x;
    if (i >= n) return;
    uint32_t key  = g_keys[i];
    uint32_t bit  = key & 31u;
    uint32_t w    = key >> 5;
    uint32_t seg  = w >> 2;          // 4 words per segment
    uint32_t widx = w & 3u;
    uint32_t r = g_segpref[seg];
    uint32_t mask = (1u << bit) - 1u;
    uint4 v = reinterpret_cast<const uint4*>(g_bitmap)[seg];
    uint32_t words[4] = {v.x, v.y, v.z, v.w};
#pragma unroll
    for (uint32_t idx = 0; idx < 4; idx++) {
        if (idx < widx)       r += __popc(words[idx]);
        else if (idx == widx) r += __popc(words[idx] & mask);
    }
    g_ranks[i] = r;
    g_inv[r] = (uint32_t)i;          // exact for singletons; racy (flagged) else
}

// D: dup processing, GRID-PARALLEL (one entry per thread): per-voxel extra
//    count, multi worklist, multi flag (bit31 of g_inv).
__global__ void k_mark() {
    uint32_t tid    = blockIdx.x * blockDim.x + threadIdx.x;
    uint32_t stride = gridDim.x * blockDim.x;
    uint32_t nd = g_ndup;
    for (uint32_t j = tid; j < nd; j += stride) {
        uint32_t r = g_ranks[g_dup[j]];
        uint32_t old = atomicAdd(&g_cnt[r], 1u);
        if (old == 0u) {                     // first dup -> new multi voxel
            uint32_t s = atomicAdd(&g_nmulti, 1u);
            g_multi[s] = r;
            atomicOr(&g_inv[r], 0x80000000u);
        }
    }
}

// E: sequential output writer. 8-lane group per slot (4 slots/warp).
//    singleton (s < nvox, flag clear) -> gather point's feats/coords;
//    else (multi or empty tail) -> zeros. Writes fully sequential.
//    Also resets g_ndup (k_mark has consumed it).
__global__ void k_gather(const int* __restrict__ coords, const float* __restrict__ feats,
                         float* __restrict__ outc, float* __restrict__ outf, int n) {
    uint32_t tid  = blockIdx.x * blockDim.x + threadIdx.x;
    if (tid == 0) g_ndup = 0u;              // restore for next call
    uint32_t gw   = tid >> 5;
    uint32_t lane = threadIdx.x & 31u;
    uint32_t q    = lane >> 3;            // 0..3: slot within warp
    uint32_t ql   = lane & 7u;
    uint32_t s    = gw * 4u + q;
    if (s >= (uint32_t)n) return;
    float4 v0 = make_float4(0.f, 0.f, 0.f, 0.f);
    float4 v1 = v0;
    float4 cf = v0;
    if (s < g_nvox) {
        uint32_t inv = g_inv[s];
        if (!(inv >> 31)) {               // singleton voxel
            uint32_t pt = inv;
            const float4* fin = reinterpret_cast<const float4*>(feats + 64ull * pt);
            v0 = __ldcs(fin + ql);
            v1 = __ldcs(fin + ql + 8);
            if (ql == 0u) {
                int4 cc = reinterpret_cast<const int4*>(coords)[pt];
                cf = make_float4((float)cc.x, (float)cc.y, (float)cc.z, (float)cc.w);
            }
        }
    }
    float4* fo = reinterpret_cast<float4*>(outf + 64ull * s);
    __stcs(fo + ql, v0);
    __stcs(fo + ql + 8, v1);
    if (ql == 0u)
        __stcs(reinterpret_cast<float4*>(outc + 4ull * s), cf);
}

// F: atomic accumulate for multi-voxel points (warp ballot + cooperative).
//    Also zeroes the bitmap for the next call (last reader was k_rank).
__global__ void k_multi(const int* __restrict__ coords, const float* __restrict__ feats,
                        float* __restrict__ outc, float* __restrict__ outf, int n) {
    uint32_t tid    = blockIdx.x * blockDim.x + threadIdx.x;
    uint32_t stride = gridDim.x * blockDim.x;
    uint4 z4 = make_uint4(0u, 0u, 0u, 0u);
    uint4* bm = reinterpret_cast<uint4*>(g_bitmap);
    for (uint32_t i = tid; i < NBM_WORDS / 4u; i += stride) bm[i] = z4;

    uint32_t gw   = tid >> 5;
    uint32_t lane = threadIdx.x & 31u;
    uint32_t pt   = gw * 32u + lane;
    bool valid = pt < (uint32_t)n;
    uint32_t r = valid ? g_ranks[pt] : 0u;
    bool multi = valid && (g_cnt[r] != 0u);
    uint32_t m = __ballot_sync(0xffffffffu, multi);
    while (m) {
        uint32_t j = __ffs(m) - 1u;
        m &= m - 1u;
        uint32_t rj  = __shfl_sync(0xffffffffu, r, j);
        uint32_t ptj = gw * 32u + j;
        float2 v = reinterpret_cast<const float2*>(feats + 64ull * ptj)[lane];
        float* fs = outf + 64ull * rj + 2ull * lane;
        atomicAdd(fs, v.x);
        atomicAdd(fs + 1, v.y);
        if (lane < 4u)
            atomicAdd(&outc[4ull * rj + lane], (float)coords[4ull * ptj + lane]);
    }
}

// G: finalize multi voxels from worklist (warp per voxel); count = g_cnt+1.
//    Lazily restores g_cnt to zero (only multi slots were touched).
__global__ void k_final(float* __restrict__ outc, float* __restrict__ outf) {
    uint32_t gw   = (blockIdx.x * blockDim.x + threadIdx.x) >> 5;
    uint32_t lane = threadIdx.x & 31u;
    uint32_t nw   = (gridDim.x * blockDim.x) >> 5;
    uint32_t nm   = g_nmulti;
    for (uint32_t v = gw; v < nm; v += nw) {
        uint32_t r = g_multi[v];
        float fc = (float)(g_cnt[r] + 1u);
        float* f = outf + 64ull * r + 2ull * lane;
        f[0] = f[0] / fc;
        f[1] = f[1] / fc;
        if (lane < 4u) {
            float* cc = outc + 4ull * r + lane;
            cc[0] = rintf(cc[0] / fc);   // half-to-even == jnp.round (exact sums)
        }
        if (lane == 0u) g_cnt[r] = 0u;   // restore for next call
    }
}

extern "C" void kernel_launch(void* const* d_in, const int* in_sizes, int n_in,
                              void* d_out, int out_size) {
    // coords is the smaller input (4 ints/point) vs feats (64 floats/point)
    const int*   coords;
    const float* feats;
    int n;
    if (in_sizes[0] <= in_sizes[1]) {
        coords = (const int*)d_in[0];
        feats  = (const float*)d_in[1];
        n = in_sizes[0] / 4;
    } else {
        coords = (const int*)d_in[1];
        feats  = (const float*)d_in[0];
        n = in_sizes[1] / 4;
    }
    if (n <= 0 || n > MAXN) return;

    float* outc = (float*)d_out;             // [n,4]  pooled coords (as f32)
    float* outf = outc + 4ull * (size_t)n;   // [n,64] pooled feats

    const int4* c4 = reinterpret_cast<const int4*>(coords);
    int nb = (n + 255) / 256;

    k_setbits<<<nb, 256>>>(c4, n);
    k_scan<<<NCHUNKB, 256>>>();
    k_rank<<<nb, 256>>>(n);
    k_mark<<<64, 256>>>();
    {
        long long warps = (n + 3) / 4;
        int blocks = (int)((warps * 32 + 255) / 256);
        k_gather<<<blocks, 256>>>(coords, feats, outc, outf, n);
    }
    k_multi<<<nb, 256>>>(coords, feats, outc, outf, n);
    k_final<<<256, 256>>>(outc, outf);
}